// round 9
// baseline (speedup 1.0000x reference)
#include <cuda_runtime.h>
#include <cstdint>
#include <cstddef>

#define C32 32
#define D8  8
#define TPB_TILES 8   // 128-row tiles per block iteration group (block = 4 warps x 32 rows x 8 iters = 1024 rows)

// ---- precomputed folded parameters (device scratch; no allocation) ----
__device__ __align__(16) float g_M1T[D8 * C32];   // M1T[d][i] = sum_j A[i][j]*W1[j][d]   (k-major B operand, k=d)
__device__ __align__(16) float g_c1[C32];         // c1[i]     = sum_j A[i][j]*b1[j]
__device__ __align__(16) float g_G2T[C32 * C32];  // G2T[k][i] = g1[k]*sum_j A[i][j]*W2[j][k] (k-major B operand)
__device__ __align__(16) float g_tbl[C32 * 4];    // per-col float4: (c2p, colsum, g2, be2)

// ============================================================================
// Precompute: normalized adjacency folded into both layers; LN1 affine folded
// into layer-2 matrix/bias (round-4 derivation, numerically verified).
// ============================================================================
__global__ void gnn_precompute_kernel(const float* __restrict__ adjacency,
                                      const float* __restrict__ W1,
                                      const float* __restrict__ b1,
                                      const float* __restrict__ W2,
                                      const float* __restrict__ b2,
                                      const float* __restrict__ g1,
                                      const float* __restrict__ be1,
                                      const float* __restrict__ g2,
                                      const float* __restrict__ be2) {
    __shared__ float A[C32][C32];
    __shared__ float dis[C32];
    __shared__ float Ms[C32][C32];   // M2T[k][i]
    __shared__ float Gs[C32][C32];   // G2T[k][i]
    int t = threadIdx.x;
    int i = t >> 5;
    int j = t & 31;

    float a = adjacency[i * C32 + j] + (i == j ? 1.0f : 0.0f);
    A[i][j] = a;
    __syncthreads();

    if (j == 0) {
        float s = 0.0f;
        #pragma unroll
        for (int k = 0; k < C32; k++) s += A[i][k];
        dis[i] = rsqrtf(s + 1e-6f);
    }
    __syncthreads();
    float na = dis[i] * A[i][j] * dis[j];
    __syncthreads();
    A[i][j] = na;   // A is now norm_adj
    __syncthreads();

    // M2T[k][i] for k = j
    {
        int k = j;
        float s = 0.0f;
        #pragma unroll
        for (int jj = 0; jj < C32; jj++) s += A[i][jj] * W2[jj * C32 + k];
        Ms[k][i] = s;
        float g = g1[k] * s;
        Gs[k][i] = g;
        g_G2T[k * C32 + i] = g;
    }
    // M1T[d][i]
    if (t < C32 * D8) {
        int ii = t >> 3;
        int d  = t & 7;
        float s = 0.0f;
        #pragma unroll
        for (int jj = 0; jj < C32; jj++) s += A[ii][jj] * W1[jj * D8 + d];
        g_M1T[d * C32 + ii] = s;
    }
    // c1
    if (t < C32) {
        float s1 = 0.0f;
        #pragma unroll
        for (int jj = 0; jj < C32; jj++) s1 += A[t][jj] * b1[jj];
        g_c1[t] = s1;
    }
    __syncthreads();

    // per-col table: c2p, colsum, g2, be2
    if (t < C32) {
        float cs = 0.0f, cp = 0.0f, c2 = 0.0f;
        #pragma unroll
        for (int k = 0; k < C32; k++) {
            cs += Gs[k][t];
            cp += be1[k] * Ms[k][t];
            c2 += A[t][k] * b2[k];
        }
        ((float4*)g_tbl)[t] = make_float4(c2 + cp, cs, g2[t], be2[t]);
    }
}

// ---- tf32 helpers ----
__device__ __forceinline__ void split_tf32(float x, uint32_t& hi, uint32_t& lo) {
    asm("cvt.rna.tf32.f32 %0, %1;" : "=r"(hi) : "f"(x));
    float r = x - __uint_as_float(hi);
    asm("cvt.rna.tf32.f32 %0, %1;" : "=r"(lo) : "f"(r));
}

// D(16x8,f32) += A(16x8,tf32,row) * B(8x8,tf32,col)
__device__ __forceinline__ void mma8(float* d, const uint32_t* a, const uint32_t* b) {
    asm volatile(
        "mma.sync.aligned.m16n8k8.row.col.f32.tf32.tf32.f32 "
        "{%0,%1,%2,%3}, {%4,%5,%6,%7}, {%8,%9}, {%0,%1,%2,%3};"
        : "+f"(d[0]), "+f"(d[1]), "+f"(d[2]), "+f"(d[3])
        : "r"(a[0]), "r"(a[1]), "r"(a[2]), "r"(a[3]), "r"(b[0]), "r"(b[1]));
}

// ============================================================================
// Main kernel: 128 threads = 4 warps; each warp owns a 32-row tile per iter,
// TPB_TILES iterations per block (1024 rows/block). Both GEMMs on tensor pipe
// via 3xTF32 m16n8k8. Per-row LN via quad shuffles (D-frag rows == A-frag rows
// == g+8s, so m/r stay thread-local). LN1 folded into layer-2 post-GEMM.
// ============================================================================
__global__ __launch_bounds__(128) void gnn_main_kernel(
    const float* __restrict__ x,
    float* __restrict__ out, int nrows) {

    __shared__ __align__(16) float4 sTBL[C32];
    __shared__ __align__(16) float  sC1[C32];
    __shared__ __align__(16) float  u_s[4][32 * 36];   // per-warp u tile, pitch 36

    int tid = threadIdx.x;
    if (tid < 32) {
        sTBL[tid] = ((const float4*)g_tbl)[tid];
        sC1[tid]  = g_c1[tid];
    }
    __syncthreads();

    int w = tid >> 5, lane = tid & 31;
    int g = lane >> 2, t = lane & 3;
    float* myu = u_s[w];

    // ---- one-time B fragments (col-major: b0=(k=t,n=8nt+g), b1=(k=t+4,n=8nt+g)) ----
    uint32_t b1h[4][2], b1l[4][2];           // layer 1 (K=8): nt x {b0,b1}
    #pragma unroll
    for (int nt = 0; nt < 4; nt++) {
        split_tf32(g_M1T[t * C32 + nt * 8 + g],       b1h[nt][0], b1l[nt][0]);
        split_tf32(g_M1T[(t + 4) * C32 + nt * 8 + g], b1h[nt][1], b1l[nt][1]);
    }
    uint32_t b2h[4][4][2], b2l[4][4][2];     // layer 2: kt x nt x {b0,b1}
    #pragma unroll
    for (int kt = 0; kt < 4; kt++)
        #pragma unroll
        for (int nt = 0; nt < 4; nt++) {
            split_tf32(g_G2T[(kt * 8 + t) * C32 + nt * 8 + g],     b2h[kt][nt][0], b2l[kt][nt][0]);
            split_tf32(g_G2T[(kt * 8 + t + 4) * C32 + nt * 8 + g], b2h[kt][nt][1], b2l[kt][nt][1]);
        }

    for (int tile = 0; tile < TPB_TILES; tile++) {
        int rowbase = (blockIdx.x * TPB_TILES + tile) * 128 + w * 32;

        // ==== layer 1: D1 = x @ M1T + c1  (A-frags straight from gmem) ====
        float D1[2][4][4];
        #pragma unroll
        for (int nt = 0; nt < 4; nt++) {
            float c0 = sC1[nt * 8 + 2 * t];
            float c1v = sC1[nt * 8 + 2 * t + 1];
            #pragma unroll
            for (int mt = 0; mt < 2; mt++) {
                D1[mt][nt][0] = c0; D1[mt][nt][1] = c1v;
                D1[mt][nt][2] = c0; D1[mt][nt][3] = c1v;
            }
        }
        #pragma unroll
        for (int mt = 0; mt < 2; mt++) {
            int ra = rowbase + g + 16 * mt;
            int rb = ra + 8;
            float f0 = (ra < nrows) ? x[(size_t)ra * D8 + t]     : 0.0f;
            float f1 = (rb < nrows) ? x[(size_t)rb * D8 + t]     : 0.0f;
            float f2 = (ra < nrows) ? x[(size_t)ra * D8 + t + 4] : 0.0f;
            float f3 = (rb < nrows) ? x[(size_t)rb * D8 + t + 4] : 0.0f;
            uint32_t ah[4], al[4];
            split_tf32(f0, ah[0], al[0]);
            split_tf32(f1, ah[1], al[1]);
            split_tf32(f2, ah[2], al[2]);
            split_tf32(f3, ah[3], al[3]);
            #pragma unroll
            for (int nt = 0; nt < 4; nt++) {
                mma8(D1[mt][nt], ah, b1h[nt]);
                mma8(D1[mt][nt], ah, b1l[nt]);
                mma8(D1[mt][nt], al, b1h[nt]);
            }
        }

        // ==== relu + LN1 stats (quad butterfly) + stage u to smem ====
        // thread's rows: g + 8*s (s = 2*mt + h); cols per D-frag: 2t, 2t+1 (+8nt)
        float m1v[4], r1v[4];
        #pragma unroll
        for (int s = 0; s < 4; s++) {
            int mt = s >> 1, h = s & 1;
            int rloc = g + 8 * s;
            float sum = 0.0f, ssq = 0.0f;
            #pragma unroll
            for (int nt = 0; nt < 4; nt++) {
                float v0 = fmaxf(D1[mt][nt][2 * h + 0], 0.0f);
                float v1 = fmaxf(D1[mt][nt][2 * h + 1], 0.0f);
                *(float2*)&myu[rloc * 36 + nt * 8 + 2 * t] = make_float2(v0, v1);
                sum += v0 + v1;
                ssq = fmaf(v0, v0, fmaf(v1, v1, ssq));
            }
            sum += __shfl_xor_sync(0xffffffffu, sum, 1);
            ssq += __shfl_xor_sync(0xffffffffu, ssq, 1);
            sum += __shfl_xor_sync(0xffffffffu, sum, 2);
            ssq += __shfl_xor_sync(0xffffffffu, ssq, 2);
            float mm = sum * (1.0f / 32.0f);
            float vv = fmaf(ssq, 1.0f / 32.0f, -mm * mm);
            m1v[s] = mm;
            r1v[s] = rsqrtf(vv + 1e-5f);
        }
        __syncwarp();

        // ==== layer 2: D2 = u @ G2T  (A-frags from smem, conflict-free) ====
        float D2[2][4][4];
        #pragma unroll
        for (int mt = 0; mt < 2; mt++)
            #pragma unroll
            for (int nt = 0; nt < 4; nt++)
                #pragma unroll
                for (int q = 0; q < 4; q++) D2[mt][nt][q] = 0.0f;

        #pragma unroll
        for (int kt = 0; kt < 4; kt++) {
            uint32_t ah[2][4], al[2][4];
            #pragma unroll
            for (int mt = 0; mt < 2; mt++) {
                int r0 = g + 16 * mt, r1 = r0 + 8;
                float f0 = myu[r0 * 36 + kt * 8 + t];
                float f1 = myu[r1 * 36 + kt * 8 + t];
                float f2 = myu[r0 * 36 + kt * 8 + t + 4];
                float f3 = myu[r1 * 36 + kt * 8 + t + 4];
                split_tf32(f0, ah[mt][0], al[mt][0]);
                split_tf32(f1, ah[mt][1], al[mt][1]);
                split_tf32(f2, ah[mt][2], al[mt][2]);
                split_tf32(f3, ah[mt][3], al[mt][3]);
            }
            #pragma unroll
            for (int mt = 0; mt < 2; mt++)
                #pragma unroll
                for (int nt = 0; nt < 4; nt++) {
                    mma8(D2[mt][nt], ah[mt], b2h[kt][nt]);
                    mma8(D2[mt][nt], ah[mt], b2l[kt][nt]);
                    mma8(D2[mt][nt], al[mt], b2h[kt][nt]);
                }
        }
        __syncwarp();   // u_s reads done before next tile's stores

        // ==== fold LN1 (h2 = c2p + r1*(D2 - m1*colsum)) + relu + LN2 stats ====
        float h2[4][8];
        float sum2[4] = {0, 0, 0, 0}, ssq2[4] = {0, 0, 0, 0};
        #pragma unroll
        for (int nt = 0; nt < 4; nt++) {
            float4 tb0 = sTBL[nt * 8 + 2 * t];
            float4 tb1 = sTBL[nt * 8 + 2 * t + 1];
            #pragma unroll
            for (int s = 0; s < 4; s++) {
                int mt = s >> 1, h = s & 1;
                float v0 = fmaf(r1v[s], fmaf(-m1v[s], tb0.y, D2[mt][nt][2 * h + 0]), tb0.x);
                float v1 = fmaf(r1v[s], fmaf(-m1v[s], tb1.y, D2[mt][nt][2 * h + 1]), tb1.x);
                v0 = fmaxf(v0, 0.0f);
                v1 = fmaxf(v1, 0.0f);
                h2[s][2 * nt] = v0;
                h2[s][2 * nt + 1] = v1;
                sum2[s] += v0 + v1;
                ssq2[s] = fmaf(v0, v0, fmaf(v1, v1, ssq2[s]));
            }
        }
        float m2v[4], r2v[4];
        #pragma unroll
        for (int s = 0; s < 4; s++) {
            float sum = sum2[s], ssq = ssq2[s];
            sum += __shfl_xor_sync(0xffffffffu, sum, 1);
            ssq += __shfl_xor_sync(0xffffffffu, ssq, 1);
            sum += __shfl_xor_sync(0xffffffffu, sum, 2);
            ssq += __shfl_xor_sync(0xffffffffu, ssq, 2);
            float mm = sum * (1.0f / 32.0f);
            float vv = fmaf(ssq, 1.0f / 32.0f, -mm * mm);
            m2v[s] = mm;
            r2v[s] = rsqrtf(vv + 1e-5f);
        }

        // ==== epilogue: out = (h2 - m2)*r2*g2 + be2, direct STG.64 ====
        // Each STG.64 instr: quads fill one 32B sector per row x 8 rows — fully
        // sector-efficient, no staging needed.
        #pragma unroll
        for (int s = 0; s < 4; s++) {
            int grow = rowbase + g + 8 * s;
            if (grow < nrows) {
                float r2 = r2v[s], m2 = m2v[s];
                float* op = out + (size_t)grow * C32;
                #pragma unroll
                for (int nt = 0; nt < 4; nt++) {
                    float4 tb0 = sTBL[nt * 8 + 2 * t];
                    float4 tb1 = sTBL[nt * 8 + 2 * t + 1];
                    float w0 = r2 * tb0.z, w1 = r2 * tb1.z;
                    float o0 = fmaf(h2[s][2 * nt],     w0, fmaf(-m2, w0, tb0.w));
                    float o1 = fmaf(h2[s][2 * nt + 1], w1, fmaf(-m2, w1, tb1.w));
                    *(float2*)&op[nt * 8 + 2 * t] = make_float2(o0, o1);
                }
            }
        }
        __syncwarp();
    }
}

extern "C" void kernel_launch(void* const* d_in, const int* in_sizes, int n_in,
                              void* d_out, int out_size) {
    const float* x         = (const float*)d_in[0];
    const float* adjacency = (const float*)d_in[1];
    const float* W1        = (const float*)d_in[2];
    const float* b1        = (const float*)d_in[3];
    const float* W2        = (const float*)d_in[4];
    const float* b2        = (const float*)d_in[5];
    const float* g1        = (const float*)d_in[6];
    const float* be1       = (const float*)d_in[7];
    const float* g2        = (const float*)d_in[8];
    const float* be2       = (const float*)d_in[9];
    float* out = (float*)d_out;

    int nrows = in_sizes[0] / D8;  // B*TF*C rows of D=8

    gnn_precompute_kernel<<<1, 1024>>>(adjacency, W1, b1, W2, b2, g1, be1, g2, be2);

    int rows_per_block = TPB_TILES * 128;
    int blocks = (nrows + rows_per_block - 1) / rows_per_block;
    gnn_main_kernel<<<blocks, 128>>>(x, out, nrows);
}

// round 10
// speedup vs baseline: 1.0869x; 1.0869x over previous
#include <cuda_runtime.h>
#include <cstdint>
#include <cstddef>

#define C32 32
#define D8  8
#define TPB_TILES 8   // block = 4 warps x 32 rows x 8 iters = 1024 rows

typedef unsigned long long ull;

// ---- precomputed folded parameters (device scratch; no allocation) ----
__device__ __align__(16) float g_M1T[D8 * C32];   // M1T[d][i] (folded layer-1 matrix)
__device__ __align__(16) float g_c1[C32];         // folded layer-1 bias
__device__ __align__(16) float g_G2T[C32 * C32];  // G2T[k][i] = g1[k]*M2T[k][i] (k-major B operand)
__device__ __align__(16) float g_tbl[C32 * 4];    // per-col float4: (c2p, colsum, g2, be2)

// ---- constant mirrors for the FFMA layer-1 (broadcast; LDC port) ----
__constant__ __align__(16) float cM1T[D8 * C32];
__constant__ __align__(16) float cc1[C32];

// ---- packed f32x2 helpers ----
__device__ __forceinline__ ull pk2(float lo, float hi) {
    ull r;
    asm("mov.b64 %0, {%1, %2};" : "=l"(r) : "f"(lo), "f"(hi));
    return r;
}
__device__ __forceinline__ void upk2(ull v, float& lo, float& hi) {
    asm("mov.b64 {%0, %1}, %2;" : "=f"(lo), "=f"(hi) : "l"(v));
}
__device__ __forceinline__ void fma2(ull& d, ull a, ull b) {
    asm("fma.rn.f32x2 %0, %1, %2, %0;" : "+l"(d) : "l"(a), "l"(b));
}
__device__ __forceinline__ void add2(ull& d, ull a) {
    asm("add.rn.f32x2 %0, %0, %1;" : "+l"(d) : "l"(a));
}

// ---- tf32 helpers ----
__device__ __forceinline__ void split_tf32(float x, uint32_t& hi, uint32_t& lo) {
    asm("cvt.rna.tf32.f32 %0, %1;" : "=r"(hi) : "f"(x));
    float r = x - __uint_as_float(hi);
    asm("cvt.rna.tf32.f32 %0, %1;" : "=r"(lo) : "f"(r));
}

// D(16x8,f32) += A(16x8,tf32,row) * B(8x8,tf32,col)
__device__ __forceinline__ void mma8(float* d, const uint32_t* a, const uint32_t* b) {
    asm volatile(
        "mma.sync.aligned.m16n8k8.row.col.f32.tf32.tf32.f32 "
        "{%0,%1,%2,%3}, {%4,%5,%6,%7}, {%8,%9}, {%0,%1,%2,%3};"
        : "+f"(d[0]), "+f"(d[1]), "+f"(d[2]), "+f"(d[3])
        : "r"(a[0]), "r"(a[1]), "r"(a[2]), "r"(a[3]), "r"(b[0]), "r"(b[1]));
}

// ============================================================================
// Precompute (unchanged math, verified through R9).
// ============================================================================
__global__ void gnn_precompute_kernel(const float* __restrict__ adjacency,
                                      const float* __restrict__ W1,
                                      const float* __restrict__ b1,
                                      const float* __restrict__ W2,
                                      const float* __restrict__ b2,
                                      const float* __restrict__ g1,
                                      const float* __restrict__ be1,
                                      const float* __restrict__ g2,
                                      const float* __restrict__ be2) {
    __shared__ float A[C32][C32];
    __shared__ float dis[C32];
    __shared__ float Ms[C32][C32];
    __shared__ float Gs[C32][C32];
    int t = threadIdx.x;
    int i = t >> 5;
    int j = t & 31;

    float a = adjacency[i * C32 + j] + (i == j ? 1.0f : 0.0f);
    A[i][j] = a;
    __syncthreads();

    if (j == 0) {
        float s = 0.0f;
        #pragma unroll
        for (int k = 0; k < C32; k++) s += A[i][k];
        dis[i] = rsqrtf(s + 1e-6f);
    }
    __syncthreads();
    float na = dis[i] * A[i][j] * dis[j];
    __syncthreads();
    A[i][j] = na;
    __syncthreads();

    {
        int k = j;
        float s = 0.0f;
        #pragma unroll
        for (int jj = 0; jj < C32; jj++) s += A[i][jj] * W2[jj * C32 + k];
        Ms[k][i] = s;
        float g = g1[k] * s;
        Gs[k][i] = g;
        g_G2T[k * C32 + i] = g;
    }
    if (t < C32 * D8) {
        int ii = t >> 3;
        int d  = t & 7;
        float s = 0.0f;
        #pragma unroll
        for (int jj = 0; jj < C32; jj++) s += A[ii][jj] * W1[jj * D8 + d];
        g_M1T[d * C32 + ii] = s;
    }
    if (t < C32) {
        float s1 = 0.0f;
        #pragma unroll
        for (int jj = 0; jj < C32; jj++) s1 += A[t][jj] * b1[jj];
        g_c1[t] = s1;
    }
    __syncthreads();

    if (t < C32) {
        float cs = 0.0f, cp = 0.0f, c2 = 0.0f;
        #pragma unroll
        for (int k = 0; k < C32; k++) {
            cs += Gs[k][t];
            cp += be1[k] * Ms[k][t];
            c2 += A[t][k] * b2[k];
        }
        ((float4*)g_tbl)[t] = make_float4(c2 + cp, cs, g2[t], be2[t]);
    }
}

// ============================================================================
// Hybrid main kernel: 128 threads = 4 warps; warp owns 32 rows per tile.
//  Layer 1: FFMA2 per-lane-row from constant port (R7 path) + thread-local LN1.
//  Layer 2: 3xTF32 m16n8k8 tensor path (R9 path), u staged via padded smem.
//  m1/r1 cross lane->frag layout via shfl.idx. LN1 affine folded into layer 2.
// ============================================================================
__global__ __launch_bounds__(128) void gnn_main_kernel(
    const float* __restrict__ x,
    float* __restrict__ out, int nrows) {

    __shared__ __align__(16) float4 sTBL[C32];
    __shared__ __align__(16) float  u_s[4][32 * 36];   // per-warp u tile, pitch 36

    int tid = threadIdx.x;
    if (tid < 32) sTBL[tid] = ((const float4*)g_tbl)[tid];
    __syncthreads();

    int w = tid >> 5, lane = tid & 31;
    int g = lane >> 2, t = lane & 3;
    float* myu = u_s[w];

    // ---- one-time layer-2 B fragments (col-major), split 3xTF32 ----
    uint32_t b2h[4][4][2], b2l[4][4][2];     // kt x nt x {b0,b1}
    #pragma unroll
    for (int kt = 0; kt < 4; kt++)
        #pragma unroll
        for (int nt = 0; nt < 4; nt++) {
            split_tf32(g_G2T[(kt * 8 + t) * C32 + nt * 8 + g],     b2h[kt][nt][0], b2l[kt][nt][0]);
            split_tf32(g_G2T[(kt * 8 + t + 4) * C32 + nt * 8 + g], b2h[kt][nt][1], b2l[kt][nt][1]);
        }

    // ---- prefetch x for tile 0 ----
    float4 xa0 = make_float4(0, 0, 0, 0), xa1 = xa0;
    {
        int row = blockIdx.x * TPB_TILES * 128 + w * 32 + lane;
        if (row < nrows) {
            const float4* xv = reinterpret_cast<const float4*>(x + (size_t)row * D8);
            xa0 = xv[0];
            xa1 = xv[1];
        }
    }

    for (int tile = 0; tile < TPB_TILES; tile++) {
        int rowbase = (blockIdx.x * TPB_TILES + tile) * 128 + w * 32;
        int row = rowbase + lane;

        // ---- prefetch next tile's x (hidden under layer-1/2 work) ----
        float4 xn0 = make_float4(0, 0, 0, 0), xn1 = xn0;
        if (tile + 1 < TPB_TILES) {
            int nr = rowbase + 128 + lane;
            if (nr < nrows) {
                const float4* xv = reinterpret_cast<const float4*>(x + (size_t)nr * D8);
                xn0 = xv[0];
                xn1 = xv[1];
            }
        }

        // ==== layer 1 (FFMA2, per-lane row, matrix+bias from constant) ====
        float xr[8] = {xa0.x, xa0.y, xa0.z, xa0.w, xa1.x, xa1.y, xa1.z, xa1.w};
        ull h[16];
        {
            const ulonglong2* cv = reinterpret_cast<const ulonglong2*>(cc1);
            #pragma unroll
            for (int q = 0; q < 8; q++) {
                ulonglong2 c = cv[q];
                h[2 * q] = c.x;
                h[2 * q + 1] = c.y;
            }
        }
        #pragma unroll
        for (int d = 0; d < D8; d++) {
            ull ad = pk2(xr[d], xr[d]);
            const ulonglong2* mr = reinterpret_cast<const ulonglong2*>(cM1T + d * C32);
            #pragma unroll
            for (int q = 0; q < 8; q++) {
                ulonglong2 mm = mr[q];
                fma2(h[2 * q],     ad, mm.x);
                fma2(h[2 * q + 1], ad, mm.y);
            }
        }

        // ==== relu + thread-local LN1 stats; stage u row to smem ====
        ull sp = 0ULL, ssp = 0ULL;
        #pragma unroll
        for (int i = 0; i < 16; i++) {
            float lo, hi;
            upk2(h[i], lo, hi);
            lo = fmaxf(lo, 0.0f);
            hi = fmaxf(hi, 0.0f);
            h[i] = pk2(lo, hi);
            add2(sp, h[i]);
            fma2(ssp, h[i], h[i]);
        }
        float s0, s1, q0, q1;
        upk2(sp, s0, s1); upk2(ssp, q0, q1);
        float m1 = (s0 + s1) * (1.0f / 32.0f);
        float v1 = (q0 + q1) * (1.0f / 32.0f) - m1 * m1;
        float r1 = rsqrtf(v1 + 1e-5f);

        float* urow = &myu[lane * 36];
        #pragma unroll
        for (int q = 0; q < 8; q++) {
            float a0, a1, a2, a3;
            upk2(h[2 * q],     a0, a1);
            upk2(h[2 * q + 1], a2, a3);
            *reinterpret_cast<float4*>(urow + 4 * q) = make_float4(a0, a1, a2, a3);
        }
        __syncwarp();

        // ---- cross m1/r1 from lane-layout to frag-layout (rows g+8s) ----
        float m1v[4], r1v[4];
        #pragma unroll
        for (int s = 0; s < 4; s++) {
            m1v[s] = __shfl_sync(0xffffffffu, m1, g + 8 * s);
            r1v[s] = __shfl_sync(0xffffffffu, r1, g + 8 * s);
        }

        // ==== layer 2: D2 = u @ G2T (3xTF32 tensor path) ====
        float D2[2][4][4];
        #pragma unroll
        for (int mt = 0; mt < 2; mt++)
            #pragma unroll
            for (int nt = 0; nt < 4; nt++)
                #pragma unroll
                for (int q = 0; q < 4; q++) D2[mt][nt][q] = 0.0f;

        #pragma unroll
        for (int kt = 0; kt < 4; kt++) {
            uint32_t ah[2][4], al[2][4];
            #pragma unroll
            for (int mt = 0; mt < 2; mt++) {
                int r0 = g + 16 * mt, r1r = r0 + 8;
                float f0 = myu[r0  * 36 + kt * 8 + t];
                float f1 = myu[r1r * 36 + kt * 8 + t];
                float f2 = myu[r0  * 36 + kt * 8 + t + 4];
                float f3 = myu[r1r * 36 + kt * 8 + t + 4];
                split_tf32(f0, ah[mt][0], al[mt][0]);
                split_tf32(f1, ah[mt][1], al[mt][1]);
                split_tf32(f2, ah[mt][2], al[mt][2]);
                split_tf32(f3, ah[mt][3], al[mt][3]);
            }
            #pragma unroll
            for (int mt = 0; mt < 2; mt++)
                #pragma unroll
                for (int nt = 0; nt < 4; nt++) {
                    mma8(D2[mt][nt], ah[mt], b2h[kt][nt]);
                    mma8(D2[mt][nt], ah[mt], b2l[kt][nt]);
                    mma8(D2[mt][nt], al[mt], b2h[kt][nt]);
                }
        }
        __syncwarp();   // u_s reads done before next tile's stores

        // ==== fold LN1 (h2 = c2p + r1*(D2 - m1*colsum)) + relu + LN2 stats ====
        float h2[4][8];
        float sum2[4] = {0, 0, 0, 0}, ssq2[4] = {0, 0, 0, 0};
        #pragma unroll
        for (int nt = 0; nt < 4; nt++) {
            float4 tb0 = sTBL[nt * 8 + 2 * t];
            float4 tb1 = sTBL[nt * 8 + 2 * t + 1];
            #pragma unroll
            for (int s = 0; s < 4; s++) {
                int mt = s >> 1, hh = s & 1;
                float v0 = fmaf(r1v[s], fmaf(-m1v[s], tb0.y, D2[mt][nt][2 * hh + 0]), tb0.x);
                float vB = fmaf(r1v[s], fmaf(-m1v[s], tb1.y, D2[mt][nt][2 * hh + 1]), tb1.x);
                v0 = fmaxf(v0, 0.0f);
                vB = fmaxf(vB, 0.0f);
                h2[s][2 * nt] = v0;
                h2[s][2 * nt + 1] = vB;
                sum2[s] += v0 + vB;
                ssq2[s] = fmaf(v0, v0, fmaf(vB, vB, ssq2[s]));
            }
        }
        float m2v[4], r2v[4];
        #pragma unroll
        for (int s = 0; s < 4; s++) {
            float sum = sum2[s], ssq = ssq2[s];
            sum += __shfl_xor_sync(0xffffffffu, sum, 1);
            ssq += __shfl_xor_sync(0xffffffffu, ssq, 1);
            sum += __shfl_xor_sync(0xffffffffu, sum, 2);
            ssq += __shfl_xor_sync(0xffffffffu, ssq, 2);
            float mm = sum * (1.0f / 32.0f);
            float vv = fmaf(ssq, 1.0f / 32.0f, -mm * mm);
            m2v[s] = mm;
            r2v[s] = rsqrtf(vv + 1e-5f);
        }

        // ==== epilogue: out = (h2 - m2)*r2*g2 + be2, direct STG.64 ====
        #pragma unroll
        for (int s = 0; s < 4; s++) {
            int grow = rowbase + g + 8 * s;
            if (grow < nrows) {
                float r2 = r2v[s], m2 = m2v[s];
                float* op = out + (size_t)grow * C32;
                #pragma unroll
                for (int nt = 0; nt < 4; nt++) {
                    float4 tb0 = sTBL[nt * 8 + 2 * t];
                    float4 tb1 = sTBL[nt * 8 + 2 * t + 1];
                    float w0 = r2 * tb0.z, w1 = r2 * tb1.z;
                    float o0 = fmaf(h2[s][2 * nt],     w0, fmaf(-m2, w0, tb0.w));
                    float o1 = fmaf(h2[s][2 * nt + 1], w1, fmaf(-m2, w1, tb1.w));
                    *(float2*)&op[nt * 8 + 2 * t] = make_float2(o0, o1);
                }
            }
        }
        __syncwarp();

        xa0 = xn0;
        xa1 = xn1;
    }
}

extern "C" void kernel_launch(void* const* d_in, const int* in_sizes, int n_in,
                              void* d_out, int out_size) {
    const float* x         = (const float*)d_in[0];
    const float* adjacency = (const float*)d_in[1];
    const float* W1        = (const float*)d_in[2];
    const float* b1        = (const float*)d_in[3];
    const float* W2        = (const float*)d_in[4];
    const float* b2        = (const float*)d_in[5];
    const float* g1        = (const float*)d_in[6];
    const float* be1       = (const float*)d_in[7];
    const float* g2        = (const float*)d_in[8];
    const float* be2       = (const float*)d_in[9];
    float* out = (float*)d_out;

    int nrows = in_sizes[0] / D8;

    gnn_precompute_kernel<<<1, 1024>>>(adjacency, W1, b1, W2, b2, g1, be1, g2, be2);

    // constant-port mirrors for layer 1 (D2D async copies; graph-capturable)
    void *pM1T, *pc1;
    cudaGetSymbolAddress(&pM1T, g_M1T);
    cudaGetSymbolAddress(&pc1,  g_c1);
    cudaMemcpyToSymbolAsync(cM1T, pM1T, D8 * C32 * sizeof(float), 0, cudaMemcpyDeviceToDevice, 0);
    cudaMemcpyToSymbolAsync(cc1,  pc1,  C32 * sizeof(float),      0, cudaMemcpyDeviceToDevice, 0);

    int rows_per_block = TPB_TILES * 128;
    int blocks = (nrows + rows_per_block - 1) / rows_per_block;
    gnn_main_kernel<<<blocks, 128>>>(x, out, nrows);
}